// round 4
// baseline (speedup 1.0000x reference)
#include <cuda_runtime.h>
#include <math.h>
#include <stdint.h>

#define HID 256
#define MAXN 50000
#define MAXE 500000

// ---------------- device scratch (no allocs allowed) ----------------
__device__ float g_h[(size_t)MAXN * HID];     // node features (residual stream)
__device__ float g_agg[(size_t)MAXN * HID];   // neighborhood sums
__device__ float g_out[(size_t)MAXN * HID];   // pre-BN layer output
__device__ float g_z1[(size_t)MAXE * HID];    // edge MLP hidden 1
__device__ float g_z2[(size_t)MAXE * HID];    // edge MLP hidden 2
__device__ int   g_counts[MAXN];
__device__ int   g_rowptr[MAXN + 1];
__device__ int   g_wp[MAXN];
__device__ int   g_srcidx[MAXE];
__device__ float g_mean[HID];
__device__ float g_m2[HID];

// ---------------- CSR build ----------------
__global__ void k_zero_counts(int n) {
    int i = blockIdx.x * blockDim.x + threadIdx.x;
    if (i < n) g_counts[i] = 0;
}

__global__ void k_count(const int* __restrict__ dst, int E) {
    int e = blockIdx.x * blockDim.x + threadIdx.x;
    if (e < E) atomicAdd(&g_counts[dst[e]], 1);
}

// single-block chunked Hillis-Steele inclusive scan -> exclusive rowptr
__global__ void k_scan(int n) {
    __shared__ int sh[1024];
    __shared__ int carry_s;
    int tid = threadIdx.x;
    if (tid == 0) { carry_s = 0; g_rowptr[0] = 0; }
    __syncthreads();
    for (int base = 0; base < n; base += 1024) {
        int i = base + tid;
        int v = (i < n) ? g_counts[i] : 0;
        sh[tid] = v;
        __syncthreads();
        for (int off = 1; off < 1024; off <<= 1) {
            int t = (tid >= off) ? sh[tid - off] : 0;
            __syncthreads();
            sh[tid] += t;
            __syncthreads();
        }
        int carry = carry_s;
        if (i < n) g_rowptr[i + 1] = carry + sh[tid];
        __syncthreads();
        if (tid == 0) carry_s = carry + sh[1023];
        __syncthreads();
    }
}

__global__ void k_copy_wp(int n) {
    int i = blockIdx.x * blockDim.x + threadIdx.x;
    if (i < n) g_wp[i] = g_rowptr[i];
}

__global__ void k_fill(const int* __restrict__ src, const int* __restrict__ dst, int E) {
    int e = blockIdx.x * blockDim.x + threadIdx.x;
    if (e < E) {
        int pos = atomicAdd(&g_wp[dst[e]], 1);
        g_srcidx[pos] = src[e];
    }
}

// ---------------- input FC: h = x @ W_in^T  (IN_CH = 2) ----------------
__global__ void k_input_fc(const float* __restrict__ x, const float* __restrict__ W_in, int N) {
    int i = blockIdx.x;
    int c = threadIdx.x;
    if (i >= N) return;
    float x0 = x[i * 2 + 0], x1 = x[i * 2 + 1];
    g_h[(size_t)i * HID + c] = x0 * W_in[c * 2 + 0] + x1 * W_in[c * 2 + 1];
}

// ---------------- aggregation: agg[i] = sum_{j in N(i)} h[j] ----------------
__global__ void k_aggregate(int N) {
    int node = blockIdx.x;
    int c = threadIdx.x;
    if (node >= N) return;
    int s = g_rowptr[node], e = g_rowptr[node + 1];
    float acc = 0.f;
    for (int p = s; p < e; p++) {
        int sidx = __ldg(&g_srcidx[p]);
        acc += g_h[(size_t)sidx * HID + c];
    }
    g_agg[(size_t)node * HID + c] = acc;
}

// ---------------- tiled GEMM: out = agg@Wa^T + h@Wb^T + bias ----------------
#define BM 64
#define BN 64
#define BK 32

__global__ void k_gemm_layer(const float* __restrict__ Wa, const float* __restrict__ Wb,
                             const float* __restrict__ bias, int M) {
    __shared__ __align__(16) float Ast[BK][BM + 4];
    __shared__ __align__(16) float Ws[BK][BN + 4];
    int m0 = blockIdx.x * BM, n0 = blockIdx.y * BN;
    int tid = threadIdx.x;
    int tx = tid & 15, ty = tid >> 4;
    int lk = tid & 31, lr = tid >> 5;
    float acc[4][4] = {};
    for (int kt = 0; kt < 2 * HID; kt += BK) {
        const float* Asrc; const float* Wsrc; int kbase;
        if (kt < HID) { Asrc = g_agg; Wsrc = Wa; kbase = kt; }
        else          { Asrc = g_h;   Wsrc = Wb; kbase = kt - HID; }
#pragma unroll
        for (int i = 0; i < BM; i += 8) {
            int mm = lr + i;
            int m = m0 + mm; if (m >= M) m = M - 1;
            Ast[lk][mm] = Asrc[(size_t)m * HID + kbase + lk];
        }
#pragma unroll
        for (int i = 0; i < BN; i += 8) {
            int nn = lr + i;
            Ws[lk][nn] = Wsrc[(size_t)(n0 + nn) * HID + kbase + lk];
        }
        __syncthreads();
#pragma unroll
        for (int kk = 0; kk < BK; kk++) {
            float4 a4 = *(const float4*)&Ast[kk][ty * 4];
            float4 b4 = *(const float4*)&Ws[kk][tx * 4];
            float a[4] = {a4.x, a4.y, a4.z, a4.w};
            float b[4] = {b4.x, b4.y, b4.z, b4.w};
#pragma unroll
            for (int i = 0; i < 4; i++)
#pragma unroll
                for (int j = 0; j < 4; j++)
                    acc[i][j] += a[i] * b[j];
        }
        __syncthreads();
    }
#pragma unroll
    for (int i = 0; i < 4; i++) {
        int m = m0 + ty * 4 + i;
        if (m >= M) continue;
#pragma unroll
        for (int j = 0; j < 4; j++) {
            int n = n0 + tx * 4 + j;
            g_out[(size_t)m * HID + n] = acc[i][j] + bias[n];
        }
    }
}

// ---------------- BN stats ----------------
__global__ void k_zero_stats() {
    int c = threadIdx.x;
    g_mean[c] = 0.f;
    g_m2[c] = 0.f;
}

__global__ void k_stats(int N) {
    int c = threadIdx.x;
    int chunk = (N + gridDim.x - 1) / gridDim.x;
    int r0 = blockIdx.x * chunk;
    int r1 = min(r0 + chunk, N);
    float s = 0.f, s2 = 0.f;
    for (int r = r0; r < r1; r++) {
        float v = g_out[(size_t)r * HID + c];
        s += v; s2 += v * v;
    }
    atomicAdd(&g_mean[c], s);
    atomicAdd(&g_m2[c], s2);
}

__global__ void k_norm_res(const float* __restrict__ gamma, const float* __restrict__ beta, int N) {
    int i = blockIdx.x, c = threadIdx.x;
    if (i >= N) return;
    float inv_n = 1.f / (float)N;
    float mu = g_mean[c] * inv_n;
    float var = g_m2[c] * inv_n - mu * mu;
    float sc = gamma[c] * rsqrtf(var + 1e-5f);
    float v = (g_out[(size_t)i * HID + c] - mu) * sc + beta[c];
    g_h[(size_t)i * HID + c] += fmaxf(v, 0.f);
}

// ---------------- edge MLP layer 1: z1 = relu(cat(h[src],h[dst]) @ W1^T + b1) ----------------
__global__ void k_gemm_edge1(const int* __restrict__ src, const int* __restrict__ dst,
                             const float* __restrict__ W1, const float* __restrict__ b1, int E) {
    __shared__ __align__(16) float Ast[BK][BM + 4];
    __shared__ __align__(16) float Ws[BK][BN + 4];
    __shared__ int ridx[2][BM];
    int m0 = blockIdx.x * BM, n0 = blockIdx.y * BN;
    int tid = threadIdx.x;
    int tx = tid & 15, ty = tid >> 4;
    int lk = tid & 31, lr = tid >> 5;
    if (tid < BM) { int e = m0 + tid; ridx[0][tid] = (e < E) ? src[e] : 0; }
    else if (tid < 2 * BM) { int t = tid - BM; int e = m0 + t; ridx[1][t] = (e < E) ? dst[e] : 0; }
    __syncthreads();
    float acc[4][4] = {};
    for (int kt = 0; kt < 2 * HID; kt += BK) {
        int half = kt >> 8;        // 0 -> src half, 1 -> dst half
        int kbase = kt & (HID - 1);
#pragma unroll
        for (int i = 0; i < BM; i += 8) {
            int mm = lr + i;
            Ast[lk][mm] = g_h[(size_t)ridx[half][mm] * HID + kbase + lk];
        }
#pragma unroll
        for (int i = 0; i < BN; i += 8) {
            int nn = lr + i;
            Ws[lk][nn] = W1[(size_t)(n0 + nn) * (2 * HID) + kt + lk];
        }
        __syncthreads();
#pragma unroll
        for (int kk = 0; kk < BK; kk++) {
            float4 a4 = *(const float4*)&Ast[kk][ty * 4];
            float4 b4 = *(const float4*)&Ws[kk][tx * 4];
            float a[4] = {a4.x, a4.y, a4.z, a4.w};
            float b[4] = {b4.x, b4.y, b4.z, b4.w};
#pragma unroll
            for (int i = 0; i < 4; i++)
#pragma unroll
                for (int j = 0; j < 4; j++)
                    acc[i][j] += a[i] * b[j];
        }
        __syncthreads();
    }
#pragma unroll
    for (int i = 0; i < 4; i++) {
        int m = m0 + ty * 4 + i;
        if (m >= E) continue;
#pragma unroll
        for (int j = 0; j < 4; j++) {
            int n = n0 + tx * 4 + j;
            g_z1[(size_t)m * HID + n] = fmaxf(acc[i][j] + b1[n], 0.f);
        }
    }
}

// ---------------- edge MLP layer 2: z2 = relu(z1 @ W2^T + b2) ----------------
__global__ void k_gemm_edge2(const float* __restrict__ W2, const float* __restrict__ b2, int E) {
    __shared__ __align__(16) float Ast[BK][BM + 4];
    __shared__ __align__(16) float Ws[BK][BN + 4];
    int m0 = blockIdx.x * BM, n0 = blockIdx.y * BN;
    int tid = threadIdx.x;
    int tx = tid & 15, ty = tid >> 4;
    int lk = tid & 31, lr = tid >> 5;
    float acc[4][4] = {};
    for (int kt = 0; kt < HID; kt += BK) {
#pragma unroll
        for (int i = 0; i < BM; i += 8) {
            int mm = lr + i;
            int m = m0 + mm; if (m >= E) m = E - 1;
            Ast[lk][mm] = g_z1[(size_t)m * HID + kt + lk];
        }
#pragma unroll
        for (int i = 0; i < BN; i += 8) {
            int nn = lr + i;
            Ws[lk][nn] = W2[(size_t)(n0 + nn) * HID + kt + lk];
        }
        __syncthreads();
#pragma unroll
        for (int kk = 0; kk < BK; kk++) {
            float4 a4 = *(const float4*)&Ast[kk][ty * 4];
            float4 b4 = *(const float4*)&Ws[kk][tx * 4];
            float a[4] = {a4.x, a4.y, a4.z, a4.w};
            float b[4] = {b4.x, b4.y, b4.z, b4.w};
#pragma unroll
            for (int i = 0; i < 4; i++)
#pragma unroll
                for (int j = 0; j < 4; j++)
                    acc[i][j] += a[i] * b[j];
        }
        __syncthreads();
    }
#pragma unroll
    for (int i = 0; i < 4; i++) {
        int m = m0 + ty * 4 + i;
        if (m >= E) continue;
#pragma unroll
        for (int j = 0; j < 4; j++) {
            int n = n0 + tx * 4 + j;
            g_z2[(size_t)m * HID + n] = fmaxf(acc[i][j] + b2[n], 0.f);
        }
    }
}

// ---------------- final: out[e] = sigmoid(dot(z2[e], W3) + b3) ----------------
__global__ void k_final(const float* __restrict__ W3, const float* __restrict__ b3,
                        float* __restrict__ out, int E) {
    __shared__ float w[HID];
    int tid = threadIdx.x;
    w[tid] = W3[tid];
    __syncthreads();
    int warp = (blockIdx.x * blockDim.x + tid) >> 5;
    int lane = tid & 31;
    if (warp >= E) return;
    const float* row = &g_z2[(size_t)warp * HID];
    float s = 0.f;
#pragma unroll
    for (int k = lane; k < HID; k += 32) s += row[k] * w[k];
#pragma unroll
    for (int off = 16; off; off >>= 1) s += __shfl_xor_sync(0xffffffffu, s, off);
    if (lane == 0) out[warp] = 1.f / (1.f + expf(-(s + b3[0])));
}

// ---------------- launch ----------------
extern "C" void kernel_launch(void* const* d_in, const int* in_sizes, int n_in,
                              void* d_out, int out_size) {
    const float* x     = (const float*)d_in[0];
    const int*   ei    = (const int*)d_in[1];
    const float* W_in  = (const float*)d_in[2];
    const float* Wrel  = (const float*)d_in[3];
    const float* brel  = (const float*)d_in[4];
    const float* Wroot = (const float*)d_in[5];
    const float* gamma = (const float*)d_in[6];
    const float* beta  = (const float*)d_in[7];
    const float* W1    = (const float*)d_in[8];
    const float* b1    = (const float*)d_in[9];
    const float* W2    = (const float*)d_in[10];
    const float* b2    = (const float*)d_in[11];
    const float* W3    = (const float*)d_in[12];
    const float* b3    = (const float*)d_in[13];
    float* out = (float*)d_out;

    int N = in_sizes[0] / 2;               // x is [N, 2]
    int E = in_sizes[1] / 2;               // edge_index is [2, E]
    int L = in_sizes[3] / (HID * HID);     // Wrel is [L, HID, HID]
    const int* src = ei;
    const int* dst = ei + E;

    // CSR build (per-launch; deterministic up to fp-add order, within tolerance)
    k_zero_counts<<<(N + 255) / 256, 256>>>(N);
    k_count<<<(E + 255) / 256, 256>>>(dst, E);
    k_scan<<<1, 1024>>>(N);
    k_copy_wp<<<(N + 255) / 256, 256>>>(N);
    k_fill<<<(E + 255) / 256, 256>>>(src, dst, E);

    // input FC
    k_input_fc<<<N, HID>>>(x, W_in, N);

    // GNN layers
    dim3 gl((N + BM - 1) / BM, HID / BN);
    for (int l = 0; l < L; l++) {
        k_aggregate<<<N, HID>>>(N);
        k_gemm_layer<<<gl, 256>>>(Wrel + (size_t)l * HID * HID,
                                  Wroot + (size_t)l * HID * HID,
                                  brel + (size_t)l * HID, N);
        k_zero_stats<<<1, HID>>>();
        k_stats<<<100, HID>>>(N);
        k_norm_res<<<N, HID>>>(gamma + (size_t)l * HID, beta + (size_t)l * HID, N);
    }

    // edge MLP
    dim3 ge((E + BM - 1) / BM, HID / BN);
    k_gemm_edge1<<<ge, 256>>>(src, dst, W1, b1, E);
    k_gemm_edge2<<<ge, 256>>>(W2, b2, E);
    k_final<<<(E + 7) / 8, 256>>>(W3, b3, out, E);
}

// round 6
// speedup vs baseline: 2.8522x; 2.8522x over previous
#include <cuda_runtime.h>
#include <math.h>
#include <stdint.h>

#define HID 256
#define MAXN 50000
#define MAXE 500000

// ---------------- device scratch (no allocs allowed) ----------------
__device__ float g_h[(size_t)MAXN * HID];     // node features (residual stream)
__device__ float g_agg[(size_t)MAXN * HID];   // neighborhood sums
__device__ float g_out[(size_t)MAXN * HID];   // pre-BN layer output
__device__ float g_z1[(size_t)MAXE * HID];    // edge MLP hidden 1
__device__ float g_logit[MAXE];               // fused edge2+W3 partial logits
__device__ int   g_counts[MAXN];
__device__ int   g_rowptr[MAXN + 1];
__device__ int   g_wp[MAXN];
__device__ int   g_srcidx[MAXE];
__device__ float g_mean[HID];                 // column sums
__device__ float g_m2[HID];                   // column sum-of-squares
__device__ float g_bnsc[HID];                 // precomputed BN scale
__device__ float g_bnsh[HID];                 // precomputed BN shift

// ---------------- CSR build ----------------
__global__ void k_zero_counts(int n) {
    int i = blockIdx.x * blockDim.x + threadIdx.x;
    if (i < n) g_counts[i] = 0;
}

__global__ void k_count(const int* __restrict__ dst, int E) {
    int e = blockIdx.x * blockDim.x + threadIdx.x;
    if (e < E) atomicAdd(&g_counts[dst[e]], 1);
}

__global__ void k_scan(int n) {
    __shared__ int sh[1024];
    __shared__ int carry_s;
    int tid = threadIdx.x;
    if (tid == 0) { carry_s = 0; g_rowptr[0] = 0; }
    __syncthreads();
    for (int base = 0; base < n; base += 1024) {
        int i = base + tid;
        int v = (i < n) ? g_counts[i] : 0;
        sh[tid] = v;
        __syncthreads();
        for (int off = 1; off < 1024; off <<= 1) {
            int t = (tid >= off) ? sh[tid - off] : 0;
            __syncthreads();
            sh[tid] += t;
            __syncthreads();
        }
        int carry = carry_s;
        if (i < n) g_rowptr[i + 1] = carry + sh[tid];
        __syncthreads();
        if (tid == 0) carry_s = carry + sh[1023];
        __syncthreads();
    }
}

__global__ void k_copy_wp(int n) {
    int i = blockIdx.x * blockDim.x + threadIdx.x;
    if (i < n) g_wp[i] = g_rowptr[i];
}

__global__ void k_fill(const int* __restrict__ src, const int* __restrict__ dst, int E) {
    int e = blockIdx.x * blockDim.x + threadIdx.x;
    if (e < E) {
        int pos = atomicAdd(&g_wp[dst[e]], 1);
        g_srcidx[pos] = src[e];
    }
}

// ---------------- input FC: h = x @ W_in^T  (IN_CH = 2) ----------------
__global__ void k_input_fc(const float* __restrict__ x, const float* __restrict__ W_in, int N) {
    int i = blockIdx.x;
    int c = threadIdx.x;
    if (i >= N) return;
    float x0 = x[i * 2 + 0], x1 = x[i * 2 + 1];
    g_h[(size_t)i * HID + c] = x0 * W_in[c * 2 + 0] + x1 * W_in[c * 2 + 1];
}

// ---------------- aggregation (float4): agg[i] = sum_{j in N(i)} h[j] ----------------
__global__ void k_aggregate(int N) {
    int node = blockIdx.x;
    int c4 = threadIdx.x;           // 64 threads, 4 channels each
    int s = g_rowptr[node], e = g_rowptr[node + 1];
    float4 acc = make_float4(0.f, 0.f, 0.f, 0.f);
    const float4* h4 = (const float4*)g_h;
    for (int p = s; p < e; p++) {
        int si = __ldg(&g_srcidx[p]);
        float4 v = h4[(size_t)si * 64 + c4];
        acc.x += v.x; acc.y += v.y; acc.z += v.z; acc.w += v.w;
    }
    ((float4*)g_agg)[(size_t)node * 64 + c4] = acc;
}

// ---------------- tf32 helpers ----------------
__device__ __forceinline__ uint32_t f2tf32(float x) {
    uint32_t r;
    asm("cvt.rna.tf32.f32 %0, %1;" : "=r"(r) : "f"(x));
    return r;
}

__device__ __forceinline__ void mma_tf32(float* c, const uint32_t* a, const uint32_t* b) {
    asm volatile(
        "mma.sync.aligned.m16n8k8.row.col.f32.tf32.tf32.f32 "
        "{%0,%1,%2,%3}, {%4,%5,%6,%7}, {%8,%9}, {%0,%1,%2,%3};"
        : "+f"(c[0]), "+f"(c[1]), "+f"(c[2]), "+f"(c[3])
        : "r"(a[0]), "r"(a[1]), "r"(a[2]), "r"(a[3]), "r"(b[0]), "r"(b[1]));
}

// ---------------- unified tensor-core GEMM ----------------
// Tile: BM=128, BN=128, BK=16; 256 threads = 8 warps (2 warp_m x 4 warp_n),
// warp tile 64x32, per warp 4x4 grid of m16n8k8 mmas per k8-substep.
//
// MODE 0: layer  — A = [g_agg | g_h] (K=512), B = [Wrel | Wroot], +bias,
//                  write g_out, fused column-stat atomics into g_mean/g_m2.
// MODE 1: edge1  — A = gathered [h[src] | h[dst]] (K=512), B = W1 (ld 512),
//                  relu -> g_z1.
// MODE 2: edge2  — A = g_z1 (K=256), B = W2, relu, dot with w3,
//                  atomicAdd partial logits (z2 never materialized).
template <int MODE>
__global__ __launch_bounds__(256)
void k_mma(const float* __restrict__ WB0, const float* __restrict__ WB1,
           const float* __restrict__ bias,
           const int* __restrict__ esrc, const int* __restrict__ edst,
           const float* __restrict__ w3, int M) {
    constexpr int KS = (MODE == 2) ? 16 : 32;     // number of BK=16 k-steps
    __shared__ __align__(16) float As[2][128][20]; // stride 20: conflict-free frag loads
    __shared__ __align__(16) float Bs[2][16][136]; // stride 136: conflict-free frag loads
    __shared__ int sidx[128];
    __shared__ int didx[128];
    __shared__ float w3s[HID];

    const int tid = threadIdx.x;
    const int m0 = blockIdx.x * 128, n0 = blockIdx.y * 128;
    const int wid = tid >> 5, lane = tid & 31;
    const int wm = wid >> 2, wn = wid & 3;
    const int g = lane >> 2, tig = lane & 3;

    if (MODE == 1) {
        if (tid < 128)      { int e = m0 + tid;      sidx[tid] = esrc[min(e, M - 1)]; }
        else                { int t = tid - 128; int e = m0 + t; didx[t] = edst[min(e, M - 1)]; }
    }
    if (MODE == 2 && tid < HID) w3s[tid] = w3[tid];
    __syncthreads();

    const int mA = tid >> 2;            // 0..63: row (x2) handled by this thread
    const int kq = (tid & 3) * 4;       // float4 column offset within BK

    float acc[4][4][4];
#pragma unroll
    for (int i = 0; i < 4; i++)
#pragma unroll
        for (int j = 0; j < 4; j++)
#pragma unroll
            for (int k = 0; k < 4; k++) acc[i][j][k] = 0.f;

    float4 pa[2], pb[2];

    // ---- address helpers ----
    auto a_ptr = [&](int kt, int mrow) -> const float* {
        if (MODE == 0) {
            const float* base = (kt < 16) ? g_agg : g_h;
            int m = min(m0 + mrow, M - 1);
            return base + (size_t)m * HID + (kt & 15) * 16 + kq;
        } else if (MODE == 1) {
            int r = (kt < 16) ? sidx[mrow] : didx[mrow];
            return g_h + (size_t)r * HID + (kt & 15) * 16 + kq;
        } else {
            int m = min(m0 + mrow, M - 1);
            return g_z1 + (size_t)m * HID + kt * 16 + kq;
        }
    };
    auto b_ptr = [&](int kt, int nrow) -> const float* {
        if (MODE == 0) {
            const float* W = (kt < 16) ? WB0 : WB1;
            return W + (size_t)(n0 + nrow) * HID + (kt & 15) * 16 + kq;
        } else if (MODE == 1) {
            return WB0 + (size_t)(n0 + nrow) * (2 * HID) + kt * 16 + kq;
        } else {
            return WB0 + (size_t)(n0 + nrow) * HID + kt * 16 + kq;
        }
    };

    auto prefetch = [&](int kt) {
        pa[0] = *(const float4*)a_ptr(kt, mA);
        pa[1] = *(const float4*)a_ptr(kt, mA + 64);
        pb[0] = *(const float4*)b_ptr(kt, mA);
        pb[1] = *(const float4*)b_ptr(kt, mA + 64);
    };
    auto stash = [&](int buf) {
#pragma unroll
        for (int h = 0; h < 2; h++) {
            float4 v = pa[h];
            uint4 t;
            t.x = f2tf32(v.x); t.y = f2tf32(v.y); t.z = f2tf32(v.z); t.w = f2tf32(v.w);
            *(uint4*)&As[buf][mA + h * 64][kq] = t;
        }
#pragma unroll
        for (int h = 0; h < 2; h++) {
            float4 v = pb[h];
            int n = mA + h * 64;
            Bs[buf][kq + 0][n] = __uint_as_float(f2tf32(v.x));
            Bs[buf][kq + 1][n] = __uint_as_float(f2tf32(v.y));
            Bs[buf][kq + 2][n] = __uint_as_float(f2tf32(v.z));
            Bs[buf][kq + 3][n] = __uint_as_float(f2tf32(v.w));
        }
    };
    auto compute = [&](int buf) {
#pragma unroll
        for (int s = 0; s < 2; s++) {
            int k0 = s * 8;
            uint32_t af[4][4], bf[4][2];
#pragma unroll
            for (int mi = 0; mi < 4; mi++) {
                int r = wm * 64 + mi * 16 + g;
                af[mi][0] = __float_as_uint(As[buf][r][k0 + tig]);
                af[mi][1] = __float_as_uint(As[buf][r + 8][k0 + tig]);
                af[mi][2] = __float_as_uint(As[buf][r][k0 + tig + 4]);
                af[mi][3] = __float_as_uint(As[buf][r + 8][k0 + tig + 4]);
            }
#pragma unroll
            for (int nj = 0; nj < 4; nj++) {
                int c = wn * 32 + nj * 8 + g;
                bf[nj][0] = __float_as_uint(Bs[buf][k0 + tig][c]);
                bf[nj][1] = __float_as_uint(Bs[buf][k0 + tig + 4][c]);
            }
#pragma unroll
            for (int mi = 0; mi < 4; mi++)
#pragma unroll
                for (int nj = 0; nj < 4; nj++)
                    mma_tf32(acc[mi][nj], af[mi], bf[nj]);
        }
    };

    // ---- mainloop: double-buffered, register prefetch ----
    prefetch(0);
    stash(0);
    __syncthreads();
    for (int kt = 0; kt < KS; kt++) {
        int buf = kt & 1;
        if (kt + 1 < KS) prefetch(kt + 1);
        compute(buf);
        if (kt + 1 < KS) stash(buf ^ 1);
        __syncthreads();
    }

    // ---- epilogues ----
    if (MODE == 0) {
        float s1[4][2], s2[4][2];
#pragma unroll
        for (int nj = 0; nj < 4; nj++) { s1[nj][0] = s1[nj][1] = s2[nj][0] = s2[nj][1] = 0.f; }
#pragma unroll
        for (int mi = 0; mi < 4; mi++) {
#pragma unroll
            for (int r = 0; r < 2; r++) {
                int m = m0 + wm * 64 + mi * 16 + g + r * 8;
                if (m < M) {
#pragma unroll
                    for (int nj = 0; nj < 4; nj++) {
                        int n = n0 + wn * 32 + nj * 8 + 2 * tig;
                        float v0 = acc[mi][nj][r * 2 + 0] + __ldg(&bias[n]);
                        float v1 = acc[mi][nj][r * 2 + 1] + __ldg(&bias[n + 1]);
                        *(float2*)&g_out[(size_t)m * HID + n] = make_float2(v0, v1);
                        s1[nj][0] += v0; s2[nj][0] += v0 * v0;
                        s1[nj][1] += v1; s2[nj][1] += v1 * v1;
                    }
                }
            }
        }
#pragma unroll
        for (int nj = 0; nj < 4; nj++)
#pragma unroll
            for (int c = 0; c < 2; c++) {
                float a = s1[nj][c], b = s2[nj][c];
#pragma unroll
                for (int off = 4; off < 32; off <<= 1) {
                    a += __shfl_xor_sync(0xffffffffu, a, off);
                    b += __shfl_xor_sync(0xffffffffu, b, off);
                }
                if (g == 0) {
                    int n = n0 + wn * 32 + nj * 8 + 2 * tig + c;
                    atomicAdd(&g_mean[n], a);
                    atomicAdd(&g_m2[n], b);
                }
            }
    } else if (MODE == 1) {
#pragma unroll
        for (int mi = 0; mi < 4; mi++) {
#pragma unroll
            for (int r = 0; r < 2; r++) {
                int m = m0 + wm * 64 + mi * 16 + g + r * 8;
                if (m < M) {
#pragma unroll
                    for (int nj = 0; nj < 4; nj++) {
                        int n = n0 + wn * 32 + nj * 8 + 2 * tig;
                        float v0 = fmaxf(acc[mi][nj][r * 2 + 0] + __ldg(&bias[n]), 0.f);
                        float v1 = fmaxf(acc[mi][nj][r * 2 + 1] + __ldg(&bias[n + 1]), 0.f);
                        *(float2*)&g_z1[(size_t)m * HID + n] = make_float2(v0, v1);
                    }
                }
            }
        }
    } else { // MODE 2: relu + dot(w3) + atomic logit
        float rs[4][2];
#pragma unroll
        for (int mi = 0; mi < 4; mi++) { rs[mi][0] = rs[mi][1] = 0.f; }
#pragma unroll
        for (int mi = 0; mi < 4; mi++) {
#pragma unroll
            for (int r = 0; r < 2; r++) {
#pragma unroll
                for (int nj = 0; nj < 4; nj++) {
                    int n = n0 + wn * 32 + nj * 8 + 2 * tig;
                    float v0 = fmaxf(acc[mi][nj][r * 2 + 0] + __ldg(&bias[n]), 0.f);
                    float v1 = fmaxf(acc[mi][nj][r * 2 + 1] + __ldg(&bias[n + 1]), 0.f);
                    rs[mi][r] += v0 * w3s[n] + v1 * w3s[n + 1];
                }
            }
        }
#pragma unroll
        for (int mi = 0; mi < 4; mi++)
#pragma unroll
            for (int r = 0; r < 2; r++) {
                float v = rs[mi][r];
                v += __shfl_xor_sync(0xffffffffu, v, 1);
                v += __shfl_xor_sync(0xffffffffu, v, 2);
                if (tig == 0) {
                    int m = m0 + wm * 64 + mi * 16 + g + r * 8;
                    if (m < M) atomicAdd(&g_logit[m], v);
                }
            }
    }
}

// ---------------- BN param precompute + fused norm/relu/residual ----------------
__global__ void k_zero_stats() {
    int c = threadIdx.x;
    g_mean[c] = 0.f;
    g_m2[c] = 0.f;
}

__global__ void k_bn_prep(const float* __restrict__ gamma, const float* __restrict__ beta, int N) {
    int c = threadIdx.x;
    float inv_n = 1.f / (float)N;
    float mu = g_mean[c] * inv_n;
    float var = g_m2[c] * inv_n - mu * mu;
    float sc = gamma[c] * rsqrtf(var + 1e-5f);
    g_bnsc[c] = sc;
    g_bnsh[c] = beta[c] - mu * sc;
}

__global__ void k_norm_res(int N) {
    int i = blockIdx.x, c4 = threadIdx.x;     // 64 threads, 4 channels each
    float4 o  = ((const float4*)g_out)[(size_t)i * 64 + c4];
    float4 hv = ((float4*)g_h)[(size_t)i * 64 + c4];
    float4 sc = ((const float4*)g_bnsc)[c4];
    float4 sh = ((const float4*)g_bnsh)[c4];
    hv.x += fmaxf(o.x * sc.x + sh.x, 0.f);
    hv.y += fmaxf(o.y * sc.y + sh.y, 0.f);
    hv.z += fmaxf(o.z * sc.z + sh.z, 0.f);
    hv.w += fmaxf(o.w * sc.w + sh.w, 0.f);
    ((float4*)g_h)[(size_t)i * 64 + c4] = hv;
}

// ---------------- edge logit zero + final sigmoid ----------------
__global__ void k_zero_logit(int E) {
    int i = blockIdx.x * blockDim.x + threadIdx.x;
    if (i < E) g_logit[i] = 0.f;
}

__global__ void k_final2(const float* __restrict__ b3, float* __restrict__ out, int E) {
    int i = blockIdx.x * blockDim.x + threadIdx.x;
    if (i < E) out[i] = 1.f / (1.f + expf(-(g_logit[i] + b3[0])));
}

// ---------------- launch ----------------
extern "C" void kernel_launch(void* const* d_in, const int* in_sizes, int n_in,
                              void* d_out, int out_size) {
    const float* x     = (const float*)d_in[0];
    const int*   ei    = (const int*)d_in[1];
    const float* W_in  = (const float*)d_in[2];
    const float* Wrel  = (const float*)d_in[3];
    const float* brel  = (const float*)d_in[4];
    const float* Wroot = (const float*)d_in[5];
    const float* gamma = (const float*)d_in[6];
    const float* beta  = (const float*)d_in[7];
    const float* W1    = (const float*)d_in[8];
    const float* b1    = (const float*)d_in[9];
    const float* W2    = (const float*)d_in[10];
    const float* b2    = (const float*)d_in[11];
    const float* W3    = (const float*)d_in[12];
    const float* b3    = (const float*)d_in[13];
    float* out = (float*)d_out;

    int N = in_sizes[0] / 2;               // x is [N, 2]
    int E = in_sizes[1] / 2;               // edge_index is [2, E]
    int L = in_sizes[3] / (HID * HID);     // Wrel is [L, HID, HID]
    const int* src = ei;
    const int* dst = ei + E;

    // CSR build
    k_zero_counts<<<(N + 255) / 256, 256>>>(N);
    k_count<<<(E + 255) / 256, 256>>>(dst, E);
    k_scan<<<1, 1024>>>(N);
    k_copy_wp<<<(N + 255) / 256, 256>>>(N);
    k_fill<<<(E + 255) / 256, 256>>>(src, dst, E);

    // input FC
    k_input_fc<<<N, HID>>>(x, W_in, N);

    // GNN layers
    dim3 gl((N + 127) / 128, 2);
    for (int l = 0; l < L; l++) {
        k_aggregate<<<N, 64>>>(N);
        k_zero_stats<<<1, HID>>>();
        k_mma<0><<<gl, 256>>>(Wrel + (size_t)l * HID * HID,
                              Wroot + (size_t)l * HID * HID,
                              brel + (size_t)l * HID,
                              nullptr, nullptr, nullptr, N);
        k_bn_prep<<<1, HID>>>(gamma + (size_t)l * HID, beta + (size_t)l * HID, N);
        k_norm_res<<<N, 64>>>(N);
    }

    // edge MLP
    dim3 ge((E + 127) / 128, 2);
    k_zero_logit<<<(E + 255) / 256, 256>>>(E);
    k_mma<1><<<ge, 256>>>(W1, nullptr, b1, src, dst, nullptr, E);
    k_mma<2><<<ge, 256>>>(W2, nullptr, b2, nullptr, nullptr, W3, E);
    k_final2<<<(E + 255) / 256, 256>>>(b3, out, E);
}

// round 7
// speedup vs baseline: 3.4204x; 1.1992x over previous
#include <cuda_runtime.h>
#include <cuda_bf16.h>
#include <math.h>
#include <stdint.h>

#define HID 256
#define MAXN 50000
#define MAXE 500000

// ---------------- device scratch (no allocs allowed) ----------------
__device__ float         g_h[(size_t)MAXN * HID];    // node features fp32 (residual master)
__device__ __nv_bfloat16 g_hb[(size_t)MAXN * HID];   // bf16 shadow of g_h (GEMM/agg input)
__device__ __nv_bfloat16 g_agg[(size_t)MAXN * HID];  // neighborhood sums (bf16)
__device__ float         g_out[(size_t)MAXN * HID];  // pre-BN layer output fp32
__device__ __nv_bfloat16 g_z1[(size_t)MAXE * HID];   // edge MLP hidden 1 (bf16)
__device__ float         g_logit[MAXE];              // fused edge2+W3 partial logits
__device__ int   g_counts[MAXN];
__device__ int   g_rowptr[MAXN + 1];
__device__ int   g_wp[MAXN];
__device__ int   g_srcidx[MAXE];
__device__ float g_mean[HID];
__device__ float g_m2[HID];
__device__ float g_bnsc[HID];
__device__ float g_bnsh[HID];

// ---------------- bf16 helpers ----------------
__device__ __forceinline__ uint32_t pack_bf16(float lo, float hi) {
    uint32_t r;
    asm("cvt.rn.bf16x2.f32 %0, %1, %2;" : "=r"(r) : "f"(hi), "f"(lo));
    return r;
}
__device__ __forceinline__ float bf_lo(uint32_t u) { return __uint_as_float(u << 16); }
__device__ __forceinline__ float bf_hi(uint32_t u) { return __uint_as_float(u & 0xffff0000u); }

// ---------------- CSR build ----------------
__global__ void k_zero_counts(int n) {
    int i = blockIdx.x * blockDim.x + threadIdx.x;
    if (i < n) g_counts[i] = 0;
}

__global__ void k_count(const int* __restrict__ dst, int E) {
    int e = blockIdx.x * blockDim.x + threadIdx.x;
    if (e < E) atomicAdd(&g_counts[dst[e]], 1);
}

__global__ void k_scan(int n) {
    __shared__ int sh[1024];
    __shared__ int carry_s;
    int tid = threadIdx.x;
    if (tid == 0) { carry_s = 0; g_rowptr[0] = 0; }
    __syncthreads();
    for (int base = 0; base < n; base += 1024) {
        int i = base + tid;
        int v = (i < n) ? g_counts[i] : 0;
        sh[tid] = v;
        __syncthreads();
        for (int off = 1; off < 1024; off <<= 1) {
            int t = (tid >= off) ? sh[tid - off] : 0;
            __syncthreads();
            sh[tid] += t;
            __syncthreads();
        }
        int carry = carry_s;
        if (i < n) g_rowptr[i + 1] = carry + sh[tid];
        __syncthreads();
        if (tid == 0) carry_s = carry + sh[1023];
        __syncthreads();
    }
}

__global__ void k_copy_wp(int n) {
    int i = blockIdx.x * blockDim.x + threadIdx.x;
    if (i < n) g_wp[i] = g_rowptr[i];
}

__global__ void k_fill(const int* __restrict__ src, const int* __restrict__ dst, int E) {
    int e = blockIdx.x * blockDim.x + threadIdx.x;
    if (e < E) {
        int pos = atomicAdd(&g_wp[dst[e]], 1);
        g_srcidx[pos] = src[e];
    }
}

// ---------------- input FC: h = x @ W_in^T  (IN_CH = 2) ----------------
__global__ void k_input_fc(const float* __restrict__ x, const float* __restrict__ W_in, int N) {
    int i = blockIdx.x;
    int c = threadIdx.x;
    if (i >= N) return;
    float x0 = x[i * 2 + 0], x1 = x[i * 2 + 1];
    float v = x0 * W_in[c * 2 + 0] + x1 * W_in[c * 2 + 1];
    g_h[(size_t)i * HID + c] = v;
    g_hb[(size_t)i * HID + c] = __float2bfloat16(v);
}

// ---------------- aggregation: agg[i] = sum_{j in N(i)} hb[j]  (bf16 in/out) ----------------
__global__ void k_aggregate(int N) {
    int node = blockIdx.x;
    int c = threadIdx.x;            // 64 threads, 4 bf16 channels each (uint2)
    int s = g_rowptr[node], e = g_rowptr[node + 1];
    float a0 = 0.f, a1 = 0.f, a2 = 0.f, a3 = 0.f;
    const uint2* hb = (const uint2*)g_hb;
    for (int p = s; p < e; p++) {
        int si = __ldg(&g_srcidx[p]);
        uint2 v = hb[(size_t)si * 64 + c];
        a0 += bf_lo(v.x); a1 += bf_hi(v.x);
        a2 += bf_lo(v.y); a3 += bf_hi(v.y);
    }
    uint2 o;
    o.x = pack_bf16(a0, a1);
    o.y = pack_bf16(a2, a3);
    ((uint2*)g_agg)[(size_t)node * 64 + c] = o;
}

// ---------------- bf16 mma ----------------
__device__ __forceinline__ void mma_bf16(float* c, const uint32_t* a, const uint32_t* b) {
    asm volatile(
        "mma.sync.aligned.m16n8k16.row.col.f32.bf16.bf16.f32 "
        "{%0,%1,%2,%3}, {%4,%5,%6,%7}, {%8,%9}, {%0,%1,%2,%3};"
        : "+f"(c[0]), "+f"(c[1]), "+f"(c[2]), "+f"(c[3])
        : "r"(a[0]), "r"(a[1]), "r"(a[2]), "r"(a[3]), "r"(b[0]), "r"(b[1]));
}

// ---------------- unified tensor-core GEMM (bf16) ----------------
// Tile: BM=128, BN=128, BK=16; 256 threads = 8 warps (2 wm x 4 wn),
// warp tile 64x32, 4x4 grid of m16n8k16 mmas per k-step.
//
// MODE 0: layer — A = [g_agg | g_hb] (K=512), B = [Wrel | Wroot] fp32->bf16,
//                 +bias, write g_out fp32, fused column-stat atomics.
// MODE 1: edge1 — A = gathered [hb[src] | hb[dst]] (K=512), B = W1 (ld 512),
//                 relu -> g_z1 (bf16).
// MODE 2: edge2 — A = g_z1 (K=256), B = W2, relu, dot w3, atomic logits.
template <int MODE>
__global__ __launch_bounds__(256)
void k_mma(const float* __restrict__ WB0, const float* __restrict__ WB1,
           const float* __restrict__ bias,
           const int* __restrict__ esrc, const int* __restrict__ edst,
           const float* __restrict__ w3, int M) {
    constexpr int KS = (MODE == 2) ? 16 : 32;           // BK=16 steps
    __shared__ __align__(16) __nv_bfloat16 As[2][128][16]; // 32B rows: conflict-free
    __shared__ __align__(16) __nv_bfloat16 Bs[2][128][16]; // n-major, same layout
    __shared__ int sidx[128];
    __shared__ int didx[128];
    __shared__ float w3s[HID];

    const int tid = threadIdx.x;
    const int m0 = blockIdx.x * 128, n0 = blockIdx.y * 128;
    const int wid = tid >> 5, lane = tid & 31;
    const int wm = wid >> 2, wn = wid & 3;
    const int g = lane >> 2, tig = lane & 3;

    if (MODE == 1) {
        if (tid < 128) { int e = m0 + tid; sidx[tid] = esrc[min(e, M - 1)]; }
        else           { int t = tid - 128; int e = m0 + t; didx[t] = edst[min(e, M - 1)]; }
    }
    if (MODE == 2 && tid < HID) w3s[tid] = w3[tid];
    __syncthreads();

    const int rowT = tid >> 1;          // 0..127: A row / B n-row this thread loads
    const int half = tid & 1;           // which 8-element half of the 16-wide k slice

    float acc[4][4][4];
#pragma unroll
    for (int i = 0; i < 4; i++)
#pragma unroll
        for (int j = 0; j < 4; j++)
#pragma unroll
            for (int k = 0; k < 4; k++) acc[i][j][k] = 0.f;

    uint4 pa;            // 8 bf16 of A
    float4 pb0, pb1;     // 8 fp32 of B (cvt at stash)

    auto a_ptr = [&](int kt) -> const uint4* {
        int kcol = (kt & 15) * 16 + half * 8;
        if (MODE == 0) {
            const __nv_bfloat16* base = (kt < 16) ? g_agg : g_hb;
            int m = min(m0 + rowT, M - 1);
            return (const uint4*)(base + (size_t)m * HID + kcol);
        } else if (MODE == 1) {
            int r = (kt < 16) ? sidx[rowT] : didx[rowT];
            return (const uint4*)(g_hb + (size_t)r * HID + kcol);
        } else {
            int m = min(m0 + rowT, M - 1);
            return (const uint4*)(g_z1 + (size_t)m * HID + kt * 16 + half * 8);
        }
    };
    auto b_ptr = [&](int kt) -> const float* {
        if (MODE == 0) {
            const float* W = (kt < 16) ? WB0 : WB1;
            return W + (size_t)(n0 + rowT) * HID + (kt & 15) * 16 + half * 8;
        } else if (MODE == 1) {
            return WB0 + (size_t)(n0 + rowT) * (2 * HID) + kt * 16 + half * 8;
        } else {
            return WB0 + (size_t)(n0 + rowT) * HID + kt * 16 + half * 8;
        }
    };

    auto prefetch = [&](int kt) {
        pa = *a_ptr(kt);
        const float* bp = b_ptr(kt);
        pb0 = *(const float4*)bp;
        pb1 = *(const float4*)(bp + 4);
    };
    auto stash = [&](int buf) {
        *(uint4*)&As[buf][rowT][half * 8] = pa;
        uint4 t;
        t.x = pack_bf16(pb0.x, pb0.y);
        t.y = pack_bf16(pb0.z, pb0.w);
        t.z = pack_bf16(pb1.x, pb1.y);
        t.w = pack_bf16(pb1.z, pb1.w);
        *(uint4*)&Bs[buf][rowT][half * 8] = t;
    };
    auto compute = [&](int buf) {
        uint32_t af[4][4], bf[4][2];
#pragma unroll
        for (int mi = 0; mi < 4; mi++) {
            int r = wm * 64 + mi * 16 + g;
            af[mi][0] = *(const uint32_t*)&As[buf][r][2 * tig];
            af[mi][1] = *(const uint32_t*)&As[buf][r + 8][2 * tig];
            af[mi][2] = *(const uint32_t*)&As[buf][r][2 * tig + 8];
            af[mi][3] = *(const uint32_t*)&As[buf][r + 8][2 * tig + 8];
        }
#pragma unroll
        for (int nj = 0; nj < 4; nj++) {
            int c = wn * 32 + nj * 8 + g;
            bf[nj][0] = *(const uint32_t*)&Bs[buf][c][2 * tig];
            bf[nj][1] = *(const uint32_t*)&Bs[buf][c][2 * tig + 8];
        }
#pragma unroll
        for (int mi = 0; mi < 4; mi++)
#pragma unroll
            for (int nj = 0; nj < 4; nj++)
                mma_bf16(acc[mi][nj], af[mi], bf[nj]);
    };

    prefetch(0);
    stash(0);
    __syncthreads();
    for (int kt = 0; kt < KS; kt++) {
        int buf = kt & 1;
        if (kt + 1 < KS) prefetch(kt + 1);
        compute(buf);
        if (kt + 1 < KS) stash(buf ^ 1);
        __syncthreads();
    }

    // ---- epilogues (C frag: c0,c1 @ (g, 2tig..+1); c2,c3 @ (g+8, ...)) ----
    if (MODE == 0) {
        float s1[4][2], s2[4][2];
#pragma unroll
        for (int nj = 0; nj < 4; nj++) { s1[nj][0] = s1[nj][1] = s2[nj][0] = s2[nj][1] = 0.f; }
#pragma unroll
        for (int mi = 0; mi < 4; mi++) {
#pragma unroll
            for (int r = 0; r < 2; r++) {
                int m = m0 + wm * 64 + mi * 16 + g + r * 8;
                if (m < M) {
#pragma unroll
                    for (int nj = 0; nj < 4; nj++) {
                        int n = n0 + wn * 32 + nj * 8 + 2 * tig;
                        float v0 = acc[mi][nj][r * 2 + 0] + __ldg(&bias[n]);
                        float v1 = acc[mi][nj][r * 2 + 1] + __ldg(&bias[n + 1]);
                        *(float2*)&g_out[(size_t)m * HID + n] = make_float2(v0, v1);
                        s1[nj][0] += v0; s2[nj][0] += v0 * v0;
                        s1[nj][1] += v1; s2[nj][1] += v1 * v1;
                    }
                }
            }
        }
#pragma unroll
        for (int nj = 0; nj < 4; nj++)
#pragma unroll
            for (int c = 0; c < 2; c++) {
                float a = s1[nj][c], b = s2[nj][c];
#pragma unroll
                for (int off = 4; off < 32; off <<= 1) {
                    a += __shfl_xor_sync(0xffffffffu, a, off);
                    b += __shfl_xor_sync(0xffffffffu, b, off);
                }
                if (g == 0) {
                    int n = n0 + wn * 32 + nj * 8 + 2 * tig + c;
                    atomicAdd(&g_mean[n], a);
                    atomicAdd(&g_m2[n], b);
                }
            }
    } else if (MODE == 1) {
#pragma unroll
        for (int mi = 0; mi < 4; mi++) {
#pragma unroll
            for (int r = 0; r < 2; r++) {
                int m = m0 + wm * 64 + mi * 16 + g + r * 8;
                if (m < M) {
#pragma unroll
                    for (int nj = 0; nj < 4; nj++) {
                        int n = n0 + wn * 32 + nj * 8 + 2 * tig;
                        float v0 = fmaxf(acc[mi][nj][r * 2 + 0] + __ldg(&bias[n]), 0.f);
                        float v1 = fmaxf(acc[mi][nj][r * 2 + 1] + __ldg(&bias[n + 1]), 0.f);
                        *(uint32_t*)&g_z1[(size_t)m * HID + n] = pack_bf16(v0, v1);
                    }
                }
            }
        }
    } else { // MODE 2: relu + dot(w3) + atomic logit
        float rs[4][2];
#pragma unroll
        for (int mi = 0; mi < 4; mi++) { rs[mi][0] = rs[mi][1] = 0.f; }
#pragma unroll
        for (int mi = 0; mi < 4; mi++) {
#pragma unroll
            for (int r = 0; r < 2; r++) {
#pragma unroll
                for (int nj = 0; nj < 4; nj++) {
                    int n = n0 + wn * 32 + nj * 8 + 2 * tig;
                    float v0 = fmaxf(acc[mi][nj][r * 2 + 0] + __ldg(&bias[n]), 0.f);
                    float v1 = fmaxf(acc[mi][nj][r * 2 + 1] + __ldg(&bias[n + 1]), 0.f);
                    rs[mi][r] += v0 * w3s[n] + v1 * w3s[n + 1];
                }
            }
        }
#pragma unroll
        for (int mi = 0; mi < 4; mi++)
#pragma unroll
            for (int r = 0; r < 2; r++) {
                float v = rs[mi][r];
                v += __shfl_xor_sync(0xffffffffu, v, 1);
                v += __shfl_xor_sync(0xffffffffu, v, 2);
                if (tig == 0) {
                    int m = m0 + wm * 64 + mi * 16 + g + r * 8;
                    if (m < M) atomicAdd(&g_logit[m], v);
                }
            }
    }
}

// ---------------- BN param precompute + fused norm/relu/residual ----------------
__global__ void k_zero_stats() {
    int c = threadIdx.x;
    g_mean[c] = 0.f;
    g_m2[c] = 0.f;
}

__global__ void k_bn_prep(const float* __restrict__ gamma, const float* __restrict__ beta, int N) {
    int c = threadIdx.x;
    float inv_n = 1.f / (float)N;
    float mu = g_mean[c] * inv_n;
    float var = g_m2[c] * inv_n - mu * mu;
    float sc = gamma[c] * rsqrtf(var + 1e-5f);
    g_bnsc[c] = sc;
    g_bnsh[c] = beta[c] - mu * sc;
}

__global__ void k_norm_res(int N) {
    int i = blockIdx.x, c4 = threadIdx.x;     // 64 threads, 4 channels each
    float4 o  = ((const float4*)g_out)[(size_t)i * 64 + c4];
    float4 hv = ((float4*)g_h)[(size_t)i * 64 + c4];
    float4 sc = ((const float4*)g_bnsc)[c4];
    float4 sh = ((const float4*)g_bnsh)[c4];
    hv.x += fmaxf(o.x * sc.x + sh.x, 0.f);
    hv.y += fmaxf(o.y * sc.y + sh.y, 0.f);
    hv.z += fmaxf(o.z * sc.z + sh.z, 0.f);
    hv.w += fmaxf(o.w * sc.w + sh.w, 0.f);
    ((float4*)g_h)[(size_t)i * 64 + c4] = hv;
    uint2 b;
    b.x = pack_bf16(hv.x, hv.y);
    b.y = pack_bf16(hv.z, hv.w);
    ((uint2*)g_hb)[(size_t)i * 64 + c4] = b;
}

// ---------------- edge logit zero + final sigmoid ----------------
__global__ void k_zero_logit(int E) {
    int i = blockIdx.x * blockDim.x + threadIdx.x;
    if (i < E) g_logit[i] = 0.f;
}

__global__ void k_final2(const float* __restrict__ b3, float* __restrict__ out, int E) {
    int i = blockIdx.x * blockDim.x + threadIdx.x;
    if (i < E) out[i] = 1.f / (1.f + expf(-(g_logit[i] + b3[0])));
}

// ---------------- launch ----------------
extern "C" void kernel_launch(void* const* d_in, const int* in_sizes, int n_in,
                              void* d_out, int out_size) {
    const float* x     = (const float*)d_in[0];
    const int*   ei    = (const int*)d_in[1];
    const float* W_in  = (const float*)d_in[2];
    const float* Wrel  = (const float*)d_in[3];
    const float* brel  = (const float*)d_in[4];
    const float* Wroot = (const float*)d_in[5];
    const float* gamma = (const float*)d_in[6];
    const float* beta  = (const float*)d_in[7];
    const float* W1    = (const float*)d_in[8];
    const float* b1    = (const float*)d_in[9];
    const float* W2    = (const float*)d_in[10];
    const float* b2    = (const float*)d_in[11];
    const float* W3    = (const float*)d_in[12];
    const float* b3    = (const float*)d_in[13];
    float* out = (float*)d_out;

    int N = in_sizes[0] / 2;               // x is [N, 2]
    int E = in_sizes[1] / 2;               // edge_index is [2, E]
    int L = in_sizes[3] / (HID * HID);     // Wrel is [L, HID, HID]
    const int* src = ei;
    const int* dst = ei + E;

    // CSR build
    k_zero_counts<<<(N + 255) / 256, 256>>>(N);
    k_count<<<(E + 255) / 256, 256>>>(dst, E);
    k_scan<<<1, 1024>>>(N);
    k_copy_wp<<<(N + 255) / 256, 256>>>(N);
    k_fill<<<(E + 255) / 256, 256>>>(src, dst, E);

    // input FC
    k_input_fc<<<N, HID>>>(x, W_in, N);

    // GNN layers
    dim3 gl((N + 127) / 128, 2);
    for (int l = 0; l < L; l++) {
        k_aggregate<<<N, 64>>>(N);
        k_zero_stats<<<1, HID>>>();
        k_mma<0><<<gl, 256>>>(Wrel + (size_t)l * HID * HID,
                              Wroot + (size_t)l * HID * HID,
                              brel + (size_t)l * HID,
                              nullptr, nullptr, nullptr, N);
        k_bn_prep<<<1, HID>>>(gamma + (size_t)l * HID, beta + (size_t)l * HID, N);
        k_norm_res<<<N, 64>>>(N);
    }

    // edge MLP
    dim3 ge((E + 127) / 128, 2);
    k_zero_logit<<<(E + 255) / 256, 256>>>(E);
    k_mma<1><<<ge, 256>>>(W1, nullptr, b1, src, dst, nullptr, E);
    k_mma<2><<<ge, 256>>>(W2, nullptr, b2, nullptr, nullptr, W3, E);
    k_final2<<<(E + 255) / 256, 256>>>(b3, out, E);
}